// round 7
// baseline (speedup 1.0000x reference)
#include <cuda_runtime.h>

#define Z_DIM 256
#define A_DIM 512
#define B_DIM 64
#define TPB 256
#define TILE_ROWS 16                       // 16 rows x 64 cols = 256 float4
#define NTILES (A_DIM / TILE_ROWS)         // 32
#define PER_Z 266432
#define OFF_H1 0
#define OFF_H2 64
#define OFF_H3 4160
#define OFF_H4 4224
#define OFF_H5 4288

__global__ __launch_bounds__(TPB) void perm_inv_fused(
    const float* __restrict__ x, float* __restrict__ out)
{
    __shared__ float4 xs[2][256];          // double-buffered 16-row tile (8 KB)
    __shared__ float  gram_s[B_DIM * B_DIM];  // 16 KB
    __shared__ float  cs_s[B_DIM];
    __shared__ float  ss_s[B_DIM];

    const int z  = blockIdx.x;
    const int t  = threadIdx.x;
    const int tx = t & 15;                 // c tile group (cols c0 = 4*tx)
    const int ty = t >> 4;                 // b tile group (rows b0 = 4*ty)

    const float4* __restrict__ xin =
        (const float4*)(x + (size_t)z * A_DIM * B_DIM);   // 8192 float4 per z

    float acc[4][4];
    #pragma unroll
    for (int i = 0; i < 4; ++i)
        #pragma unroll
        for (int j = 0; j < 4; ++j) acc[i][j] = 0.f;

    float4 cs4 = make_float4(0.f, 0.f, 0.f, 0.f);
    float4 ss4 = make_float4(0.f, 0.f, 0.f, 0.f);

    // ---- prologue: tile 0 ----
    {
        float4 g = xin[t];
        xs[0][t] = g;
        cs4.x += g.x; cs4.y += g.y; cs4.z += g.z; cs4.w += g.w;
        ss4.x += g.x * g.x; ss4.y += g.y * g.y;
        ss4.z += g.z * g.z; ss4.w += g.w * g.w;
    }
    __syncthreads();

    // ---- mainloop: gram accumulation, double-buffered ----
    for (int tile = 0; tile < NTILES; ++tile) {
        const int cur = tile & 1;
        float4 gn;
        const bool more = (tile + 1 < NTILES);
        if (more) gn = xin[(tile + 1) * 256 + t];   // prefetch next tile

        #pragma unroll
        for (int r = 0; r < TILE_ROWS; ++r) {
            float4 vb = xs[cur][r * 16 + ty];
            float4 vc = xs[cur][r * 16 + tx];
            acc[0][0] += vb.x * vc.x; acc[0][1] += vb.x * vc.y;
            acc[0][2] += vb.x * vc.z; acc[0][3] += vb.x * vc.w;
            acc[1][0] += vb.y * vc.x; acc[1][1] += vb.y * vc.y;
            acc[1][2] += vb.y * vc.z; acc[1][3] += vb.y * vc.w;
            acc[2][0] += vb.z * vc.x; acc[2][1] += vb.z * vc.y;
            acc[2][2] += vb.z * vc.z; acc[2][3] += vb.z * vc.w;
            acc[3][0] += vb.w * vc.x; acc[3][1] += vb.w * vc.y;
            acc[3][2] += vb.w * vc.z; acc[3][3] += vb.w * vc.w;
        }

        if (more) {
            xs[cur ^ 1][t] = gn;                    // other buffer: no race
            cs4.x += gn.x; cs4.y += gn.y; cs4.z += gn.z; cs4.w += gn.w;
            ss4.x += gn.x * gn.x; ss4.y += gn.y * gn.y;
            ss4.z += gn.z * gn.z; ss4.w += gn.w * gn.w;
        }
        __syncthreads();
    }

    // ---- reduce cs / ssq partials (reuse xs buffers) ----
    xs[0][t] = cs4;
    xs[1][t] = ss4;

    // ---- gram -> smem ----
    #pragma unroll
    for (int i = 0; i < 4; ++i)
        #pragma unroll
        for (int j = 0; j < 4; ++j)
            gram_s[(ty * 4 + i) * B_DIM + (tx * 4 + j)] = acc[i][j];
    __syncthreads();

    if (t < 16) {
        float4 sc = make_float4(0.f, 0.f, 0.f, 0.f);
        float4 sq = make_float4(0.f, 0.f, 0.f, 0.f);
        #pragma unroll
        for (int k = 0; k < 16; ++k) {
            float4 a = xs[0][k * 16 + t];
            float4 b = xs[1][k * 16 + t];
            sc.x += a.x; sc.y += a.y; sc.z += a.z; sc.w += a.w;
            sq.x += b.x; sq.y += b.y; sq.z += b.z; sq.w += b.w;
        }
        ((float4*)cs_s)[t] = sc;
        ((float4*)ss_s)[t] = sq;
    }
    __syncthreads();

    float* __restrict__ oz = out + (size_t)z * PER_Z;

    // ---- h2: gram, coalesced float4 copy (4096 floats = 1024 float4) ----
    {
        float4* o2 = (float4*)(oz + OFF_H2);
        const float4* g4 = (const float4*)gram_s;
        #pragma unroll
        for (int i = 0; i < 4; ++i) {
            float4 v = g4[t + i * 256];
            __stcs(&o2[t + i * 256], v);
        }
    }

    // ---- h1, h3, h4 ----
    if (t < B_DIM) {
        float c = cs_s[t];
        oz[OFF_H1 + t] = c;
        oz[OFF_H3 + t] = ss_s[t];
        oz[OFF_H4 + t] = c * c;
    }

    // ---- h5: out[b*4096 + c*64 + d] = gram[b,c] * cs[d] ----
    // float4 index idx4 = it*256 + t; d-group = t&15 (constant per thread),
    // bc = it*16 + (t>>4). cs float4 hoisted into registers.
    {
        const float4 c4 = ((const float4*)cs_s)[tx];
        float4* o5 = (float4*)(oz + OFF_H5);
        const int bc0 = ty;                // t >> 4
        #pragma unroll 4
        for (int it = 0; it < 256; ++it) {
            float gv = gram_s[bc0 + it * 16];
            float4 v = make_float4(gv * c4.x, gv * c4.y, gv * c4.z, gv * c4.w);
            __stcs(&o5[it * 256 + t], v);
        }
    }
}

extern "C" void kernel_launch(void* const* d_in, const int* in_sizes, int n_in,
                              void* d_out, int out_size)
{
    (void)in_sizes; (void)n_in; (void)out_size;
    const float* x = (const float*)d_in[0];
    float* out = (float*)d_out;
    perm_inv_fused<<<Z_DIM, TPB>>>(x, out);
}

// round 8
// speedup vs baseline: 1.0602x; 1.0602x over previous
#include <cuda_runtime.h>

#define Z_DIM 256
#define A_DIM 512
#define B_DIM 64
#define TPB 256
#define TILE_ROWS 16                       // 16 rows x 64 cols = 256 float4
#define NTILES (A_DIM / TILE_ROWS)         // 32
#define PER_Z 266432
#define OFF_H1 0
#define OFF_H2 64
#define OFF_H3 4160
#define OFF_H4 4224
#define OFF_H5 4288

__global__ __launch_bounds__(TPB) void perm_inv_fused(
    const float* __restrict__ x, float* __restrict__ out)
{
    __shared__ float4 xs[2][256];          // double-buffered 16-row tile (8 KB)
    __shared__ float  gram_s[B_DIM * B_DIM];  // 16 KB
    __shared__ float  cs_s[B_DIM];
    __shared__ float  ss_s[B_DIM];

    const int z  = blockIdx.x;
    const int t  = threadIdx.x;
    const int tx = t & 15;                 // c tile group (cols c0 = 4*tx)
    const int ty = t >> 4;                 // b tile group (rows b0 = 4*ty)

    const float4* __restrict__ xin =
        (const float4*)(x + (size_t)z * A_DIM * B_DIM);   // 8192 float4 per z

    float acc[4][4];
    #pragma unroll
    for (int i = 0; i < 4; ++i)
        #pragma unroll
        for (int j = 0; j < 4; ++j) acc[i][j] = 0.f;

    float4 cs4 = make_float4(0.f, 0.f, 0.f, 0.f);
    float4 ss4 = make_float4(0.f, 0.f, 0.f, 0.f);

    // ---- prologue: tile 0 ----
    {
        float4 g = xin[t];
        xs[0][t] = g;
        cs4.x += g.x; cs4.y += g.y; cs4.z += g.z; cs4.w += g.w;
        ss4.x += g.x * g.x; ss4.y += g.y * g.y;
        ss4.z += g.z * g.z; ss4.w += g.w * g.w;
    }
    __syncthreads();

    // ---- mainloop: gram accumulation, double-buffered ----
    for (int tile = 0; tile < NTILES; ++tile) {
        const int cur = tile & 1;
        float4 gn;
        const bool more = (tile + 1 < NTILES);
        if (more) gn = xin[(tile + 1) * 256 + t];   // prefetch next tile

        #pragma unroll
        for (int r = 0; r < TILE_ROWS; ++r) {
            float4 vb = xs[cur][r * 16 + ty];
            float4 vc = xs[cur][r * 16 + tx];
            acc[0][0] += vb.x * vc.x; acc[0][1] += vb.x * vc.y;
            acc[0][2] += vb.x * vc.z; acc[0][3] += vb.x * vc.w;
            acc[1][0] += vb.y * vc.x; acc[1][1] += vb.y * vc.y;
            acc[1][2] += vb.y * vc.z; acc[1][3] += vb.y * vc.w;
            acc[2][0] += vb.z * vc.x; acc[2][1] += vb.z * vc.y;
            acc[2][2] += vb.z * vc.z; acc[2][3] += vb.z * vc.w;
            acc[3][0] += vb.w * vc.x; acc[3][1] += vb.w * vc.y;
            acc[3][2] += vb.w * vc.z; acc[3][3] += vb.w * vc.w;
        }

        if (more) {
            xs[cur ^ 1][t] = gn;                    // other buffer: no race
            cs4.x += gn.x; cs4.y += gn.y; cs4.z += gn.z; cs4.w += gn.w;
            ss4.x += gn.x * gn.x; ss4.y += gn.y * gn.y;
            ss4.z += gn.z * gn.z; ss4.w += gn.w * gn.w;
        }
        __syncthreads();
    }

    // ---- reduce cs / ssq partials (reuse xs buffers) ----
    xs[0][t] = cs4;
    xs[1][t] = ss4;

    // ---- gram -> smem ----
    #pragma unroll
    for (int i = 0; i < 4; ++i)
        #pragma unroll
        for (int j = 0; j < 4; ++j)
            gram_s[(ty * 4 + i) * B_DIM + (tx * 4 + j)] = acc[i][j];
    __syncthreads();

    if (t < 16) {
        float4 sc = make_float4(0.f, 0.f, 0.f, 0.f);
        float4 sq = make_float4(0.f, 0.f, 0.f, 0.f);
        #pragma unroll
        for (int k = 0; k < 16; ++k) {
            float4 a = xs[0][k * 16 + t];
            float4 b = xs[1][k * 16 + t];
            sc.x += a.x; sc.y += a.y; sc.z += a.z; sc.w += a.w;
            sq.x += b.x; sq.y += b.y; sq.z += b.z; sq.w += b.w;
        }
        ((float4*)cs_s)[t] = sc;
        ((float4*)ss_s)[t] = sq;
    }
    __syncthreads();

    float* __restrict__ oz = out + (size_t)z * PER_Z;

    // ---- h2: gram, coalesced float4 copy (4096 floats = 1024 float4) ----
    {
        float4* o2 = (float4*)(oz + OFF_H2);
        const float4* g4 = (const float4*)gram_s;
        #pragma unroll
        for (int i = 0; i < 4; ++i) {
            float4 v = g4[t + i * 256];
            __stcs(&o2[t + i * 256], v);
        }
    }

    // ---- h1, h3, h4 ----
    if (t < B_DIM) {
        float c = cs_s[t];
        oz[OFF_H1 + t] = c;
        oz[OFF_H3 + t] = ss_s[t];
        oz[OFF_H4 + t] = c * c;
    }

    // ---- h5: out[b*4096 + c*64 + d] = gram[b,c] * cs[d] ----
    // float4 index idx4 = it*256 + t; d-group = t&15 (constant per thread),
    // bc = it*16 + (t>>4). cs float4 hoisted into registers.
    {
        const float4 c4 = ((const float4*)cs_s)[tx];
        float4* o5 = (float4*)(oz + OFF_H5);
        const int bc0 = ty;                // t >> 4
        #pragma unroll 4
        for (int it = 0; it < 256; ++it) {
            float gv = gram_s[bc0 + it * 16];
            float4 v = make_float4(gv * c4.x, gv * c4.y, gv * c4.z, gv * c4.w);
            __stcs(&o5[it * 256 + t], v);
        }
    }
}

extern "C" void kernel_launch(void* const* d_in, const int* in_sizes, int n_in,
                              void* d_out, int out_size)
{
    (void)in_sizes; (void)n_in; (void)out_size;
    const float* x = (const float*)d_in[0];
    float* out = (float*)d_out;
    perm_inv_fused<<<Z_DIM, TPB>>>(x, out);
}